// round 16
// baseline (speedup 1.0000x reference)
#include <cuda_runtime.h>
#include <cuda_fp16.h>
#include <math.h>
#include <stdint.h>

// Problem constants
#define BSZ    4096
#define NST    4
#define EMBED  2048
#define DFF    8192
#define IN_DIM 8192   // N*BLOCK = 4*2048
#define BLK    2048

// Scratch (device globals; no allocations allowed)
__device__ __half g_branch[(size_t)BSZ * EMBED];  // 16 MB fp16
__device__ __half g_H[(size_t)BSZ * DFF];         // 64 MB fp16
__device__ float  g_wout[BSZ * NST];
__device__ float  g_phi[BSZ * 16];                // per-row Phi (4x4)
__device__ __half g_W1h[(size_t)EMBED * DFF];     // fp16(W1) [2048, 8192]
__device__ __half g_W2h[(size_t)DFF * EMBED];     // fp16(W2) [8192, 2048]
__device__ __half g_Wsm[30 * IN_DIM];             // packed small weights (fp16)

// ---------------------------------------------------------------------------
// Math helpers
// ---------------------------------------------------------------------------
__device__ __forceinline__ float sigf(float v) { return 1.0f / (1.0f + expf(-v)); }
__device__ __forceinline__ float softplusf(float v) {
    return (v > 15.0f) ? v : log1pf(expf(v));
}
__device__ __forceinline__ float geluf(float v) {
    const float c = 0.7978845608028654f;
    float t = tanhf(c * (v + 0.044715f * v * v * v));
    return 0.5f * v * (1.0f + t);
}
__device__ __forceinline__ void mma_f16(float* c, const uint32_t* a, const uint32_t* b) {
    asm volatile("mma.sync.aligned.m16n8k16.row.col.f32.f16.f16.f32 "
                 "{%0,%1,%2,%3}, {%4,%5,%6,%7}, {%8,%9}, {%0,%1,%2,%3};"
                 : "+f"(c[0]), "+f"(c[1]), "+f"(c[2]), "+f"(c[3])
                 : "r"(a[0]), "r"(a[1]), "r"(a[2]), "r"(a[3]),
                   "r"(b[0]), "r"(b[1]));
}
__device__ __forceinline__ void ldsm_x4(uint32_t* r, uint32_t addr) {
    asm volatile("ldmatrix.sync.aligned.m8n8.x4.shared.b16 {%0,%1,%2,%3}, [%4];"
                 : "=r"(r[0]), "=r"(r[1]), "=r"(r[2]), "=r"(r[3]) : "r"(addr));
}
__device__ __forceinline__ void ldsm_x4_trans(uint32_t* r, uint32_t addr) {
    asm volatile("ldmatrix.sync.aligned.m8n8.x4.trans.shared.b16 {%0,%1,%2,%3}, [%4];"
                 : "=r"(r[0]), "=r"(r[1]), "=r"(r[2]), "=r"(r[3]) : "r"(addr));
}
__device__ __forceinline__ void cp16(uint32_t s, const void* g) {
    asm volatile("cp.async.cg.shared.global [%0], [%1], 16;" :: "r"(s), "l"(g));
}
__device__ __forceinline__ void cp_commit() {
    asm volatile("cp.async.commit_group;" ::: "memory");
}
template<int N>
__device__ __forceinline__ void cp_wait() {
    asm volatile("cp.async.wait_group %0;" :: "n"(N) : "memory");
}
__device__ __forceinline__ uint32_t smem_u32(const void* p) {
    uint32_t a;
    asm("{ .reg .u64 t; cvta.to.shared.u64 t, %1; cvt.u32.u64 %0, t; }" : "=r"(a) : "l"(p));
    return a;
}

// ---------------------------------------------------------------------------
// f32 -> f16 weight conversion (W1 / W2)
// ---------------------------------------------------------------------------
__global__ void __launch_bounds__(256) f16_copy4(const float4* __restrict__ src,
                                                 uint2* __restrict__ dst, int n4)
{
    int i = blockIdx.x * blockDim.x + threadIdx.x;
    if (i < n4) {
        float4 v = src[i];
        __half2 h0 = __floats2half2_rn(v.x, v.y);
        __half2 h1 = __floats2half2_rn(v.z, v.w);
        uint2 o;
        o.x = *(uint32_t*)&h0;
        o.y = *(uint32_t*)&h1;
        dst[i] = o;
    }
}

// ---------------------------------------------------------------------------
// Pack small weights to fp16 in dot-index order:
// j: 0-3 W_ri, 4-7 W_wo, 8-23 W_conv, 24-27 W_diss, 28 W_dtc, 29 W_dtd
// ---------------------------------------------------------------------------
__global__ void __launch_bounds__(256) pack_wsm(
    const float* __restrict__ W_ri,  const float* __restrict__ W_wo,
    const float* __restrict__ W_conv, const float* __restrict__ W_diss,
    const float* __restrict__ W_dtc, const float* __restrict__ W_dtd)
{
    const int i = blockIdx.x * blockDim.x + threadIdx.x;   // float4 units
    const int total = 30 * IN_DIM / 4;
    if (i >= total) return;
    const int j  = i / (IN_DIM / 4);
    const int kc = i % (IN_DIM / 4);
    const float* src;
    if (j < 4)        src = W_ri   + (size_t)j        * IN_DIM;
    else if (j < 8)   src = W_wo   + (size_t)(j - 4)  * IN_DIM;
    else if (j < 24)  src = W_conv + (size_t)(j - 8)  * IN_DIM;
    else if (j < 28)  src = W_diss + (size_t)(j - 24) * IN_DIM;
    else if (j == 28) src = W_dtc;
    else              src = W_dtd;
    float4 v = *(const float4*)(src + kc * 4);
    __half2 h0 = __floats2half2_rn(v.x, v.y);
    __half2 h1 = __floats2half2_rn(v.z, v.w);
    uint2 o;
    o.x = *(uint32_t*)&h0;
    o.y = *(uint32_t*)&h1;
    *(uint2*)(g_Wsm + (size_t)j * IN_DIM + kc * 4) = o;
}

// ---------------------------------------------------------------------------
// Kernel A: 4 rows per CTA, warp-split reduction, fp16 weights (half the
// L2 weight traffic). Writes g_branch, g_wout, g_phi.
// ---------------------------------------------------------------------------
__global__ void __launch_bounds__(256) kernelA(
    const float* __restrict__ x,
    const float* __restrict__ p_ri,   const float* __restrict__ p_wo,
    const float* __restrict__ a_ri,   const float* __restrict__ a_wo,
    const float* __restrict__ ldt_c,  const float* __restrict__ ldt_d,
    const float* __restrict__ b_dtc,  const float* __restrict__ b_dtd,
    const float* __restrict__ cA,     const float* __restrict__ ddiag)
{
    extern __shared__ float sx[];          // [4 * IN_DIM] = 128KB
    __shared__ float sdots[32][4];
    __shared__ float srin[4][4];

    const int row0 = blockIdx.x * 4;
    const int tid = threadIdx.x;
    const int w = tid >> 5, lane = tid & 31;

    {
        const float4* xr = (const float4*)(x + (size_t)row0 * IN_DIM);
        float4* sx4 = (float4*)sx;
        #pragma unroll 4
        for (int i = tid; i < 4 * IN_DIM / 4; i += 256) sx4[i] = xr[i];
    }
    __syncthreads();

    const __half* wp[4];
    int jidx[4];
    #pragma unroll
    for (int jj = 0; jj < 4; jj++) {
        const int j = w * 4 + jj;
        jidx[jj] = j;
        wp[jj] = g_Wsm + (size_t)((j < 30) ? j : 0) * IN_DIM;
    }

    float acc[4][4];
    #pragma unroll
    for (int a0 = 0; a0 < 4; a0++)
        #pragma unroll
        for (int a1 = 0; a1 < 4; a1++) acc[a0][a1] = 0.0f;

    #pragma unroll 4
    for (int k = lane; k < IN_DIM; k += 32) {
        const float x0 = sx[k];
        const float x1 = sx[IN_DIM + k];
        const float x2 = sx[2 * IN_DIM + k];
        const float x3 = sx[3 * IN_DIM + k];
        #pragma unroll
        for (int jj = 0; jj < 4; jj++) {
            if (jidx[jj] == 30) {
                acc[jj][0] = fmaf(x0, x0, acc[jj][0]);
                acc[jj][1] = fmaf(x1, x1, acc[jj][1]);
                acc[jj][2] = fmaf(x2, x2, acc[jj][2]);
                acc[jj][3] = fmaf(x3, x3, acc[jj][3]);
            } else {
                const float wv = __half2float(__ldg(wp[jj] + k));
                acc[jj][0] = fmaf(wv, x0, acc[jj][0]);
                acc[jj][1] = fmaf(wv, x1, acc[jj][1]);
                acc[jj][2] = fmaf(wv, x2, acc[jj][2]);
                acc[jj][3] = fmaf(wv, x3, acc[jj][3]);
            }
        }
    }

    #pragma unroll
    for (int jj = 0; jj < 4; jj++)
        #pragma unroll
        for (int r = 0; r < 4; r++) {
            float v = acc[jj][r];
            #pragma unroll
            for (int o = 16; o > 0; o >>= 1) v += __shfl_down_sync(0xffffffffu, v, o);
            if (lane == 0) sdots[w * 4 + jj][r] = v;
        }
    __syncthreads();

    if (tid < 4) {
        const int r = tid;
        const int row = row0 + r;
        const float rstd = rsqrtf(sdots[30][r] * (1.0f / (float)IN_DIM) + 1.1920929e-7f);
        float h[30];
        #pragma unroll
        for (int j = 0; j < 30; j++) h[j] = sdots[j][r] * rstd;

        const float ari = a_ri[0], awo = a_wo[0];
        #pragma unroll
        for (int n = 0; n < 4; n++) {
            srin[r][n] = sigf(ari * h[n] + p_ri[n]);
            g_wout[row * 4 + n] = 2.0f * sigf(awo * h[4 + n] + p_wo[n]);
        }

        const float dtc = 1e-3f + 0.999f * sigf(ldt_c[0] + h[28] + b_dtc[0]);
        const float dtd = 1e-3f + 0.999f * sigf(ldt_d[0] + h[29] + b_dtd[0]);

        float Mm[4][4];
        #pragma unroll
        for (int i = 0; i < 4; i++)
            #pragma unroll
            for (int j = 0; j < 4; j++)
                Mm[i][j] = cA[i * 4 + j] + h[8 + i * 4 + j];

        float S[4][4];
        #pragma unroll
        for (int i = 0; i < 4; i++)
            #pragma unroll
            for (int j = 0; j < 4; j++)
                S[i][j] = 0.5f * (Mm[i][j] - Mm[j][i]) * dtc;

        float ehD[4];
        #pragma unroll
        for (int n = 0; n < 4; n++) {
            float dd = softplusf(ddiag[n] + h[24 + n]);
            ehD[n] = expf(-0.5f * dtd * dd);
        }

        float A[4][4], X[4][4];
        #pragma unroll
        for (int i = 0; i < 4; i++)
            #pragma unroll
            for (int j = 0; j < 4; j++) {
                float id = (i == j) ? 1.0f : 0.0f;
                A[i][j] = id - S[i][j];
                X[i][j] = id + S[i][j];
            }
        #pragma unroll
        for (int p = 0; p < 4; p++) {
            float inv = 1.0f / A[p][p];
            #pragma unroll
            for (int j = 0; j < 4; j++) { A[p][j] *= inv; X[p][j] *= inv; }
            #pragma unroll
            for (int rr = 0; rr < 4; rr++) {
                if (rr == p) continue;
                float f = A[rr][p];
                #pragma unroll
                for (int j = 0; j < 4; j++) {
                    A[rr][j] = fmaf(-f, A[p][j], A[rr][j]);
                    X[rr][j] = fmaf(-f, X[p][j], X[rr][j]);
                }
            }
        }
        #pragma unroll
        for (int i = 0; i < 4; i++)
            #pragma unroll
            for (int j = 0; j < 4; j++)
                g_phi[row * 16 + i * 4 + j] = ehD[i] * X[i][j] * ehD[j];
    }
    __syncthreads();

    // Phase 3: branch only (fp16)
    #pragma unroll
    for (int r = 0; r < 4; r++) {
        const int row = row0 + r;
        const float* sxr = sx + r * IN_DIM;
        const float r0 = srin[r][0], r1 = srin[r][1], r2 = srin[r][2], r3 = srin[r][3];
        for (int c = tid; c < BLK; c += 256) {
            float x0 = sxr[c], x1 = sxr[BLK + c], x2 = sxr[2 * BLK + c], x3 = sxr[3 * BLK + c];
            g_branch[(size_t)row * BLK + c] =
                __float2half_rn(r0 * x0 + r1 * x1 + r2 * x2 + r3 * x3);
        }
    }
}

// ---------------------------------------------------------------------------
// FP16 mma.sync GEMM (R12/R15 mainloop): CTA 128x128, BK=64, 256 threads
// (8 warps, warp 32x64), 2-stage cp.async, 2 CTAs/SM.
// PHASE 1: g_H = f16(gelu(g_branch @ W1h))           (Kdim=2048, Ndim=8192)
// PHASE 2: out = Phi@x + wout * (g_H @ W2h) (pure store; Kdim=8192, Ndim=2048)
// ---------------------------------------------------------------------------
#define GBM 128
#define GBN 128
#define GBK 64
#define ASTRB 144                    // bytes/row: 64 fp16 + 8 pad
#define BSTRB 272                    // bytes/row: 128 fp16 + 8 pad
#define A_STAGE_B (GBM * ASTRB)      // 18432 B
#define B_STAGE_B (GBK * BSTRB)      // 17408 B
#define STAGE_B   (A_STAGE_B + B_STAGE_B)   // 35840 B
#define GEMM_SMEM (2 * STAGE_B)             // 71680 B -> 2 CTAs/SM = 143KB

template<int Kdim, int Ndim, int PHASE>
__global__ void __launch_bounds__(256, 2) tc_gemm(
    const __half* __restrict__ Ag,
    const __half* __restrict__ Bg,
    __half* __restrict__ CoutH,      // PHASE 1 target
    float* __restrict__ CoutF,       // PHASE 2 target
    const float* __restrict__ xg)    // PHASE 2: original x (for Phi@x)
{
    extern __shared__ char smem[];
    const uint32_t sb = smem_u32(smem);

    const int tid  = threadIdx.x;
    const int wid  = tid >> 5;
    const int lane = tid & 31;
    const int g = lane >> 2, t = lane & 3;
    const int l15 = lane & 15;
    const int lhi = lane >> 4;           // 0/1
    const int wm = (wid & 3) * 32;       // 4 warps along M (128)
    const int wn = (wid >> 2) * 64;      // 2 warps along N (128)
    const int bm = blockIdx.y * GBM;
    const int bn = blockIdx.x * GBN;

    // accumulators: warp tile 32x64 -> mt=2 (m16), nt=8 (n8) = 64 regs
    float acc[2][8][4];
    #pragma unroll
    for (int i = 0; i < 2; i++)
        #pragma unroll
        for (int j = 0; j < 8; j++)
            #pragma unroll
            for (int q = 0; q < 4; q++) acc[i][j][q] = 0.0f;

    auto load_stage = [&](int stage, int buf) {
        const uint32_t Ab = sb + buf * STAGE_B;
        const uint32_t Bb = Ab + A_STAGE_B;
        const int k0 = stage * GBK;
        // A: 128 rows x 8 16B-chunks = 1024 chunks, 4/thread
        #pragma unroll
        for (int j = 0; j < 4; j++) {
            const int c = tid + j * 256;
            const int row = c >> 3, kc = c & 7;
            cp16(Ab + (uint32_t)(row * ASTRB + kc * 16),
                 Ag + (size_t)(bm + row) * Kdim + k0 + kc * 8);
        }
        // B: 64 rows x 16 16B-chunks (128 fp16/row) = 1024 chunks, 4/thread
        #pragma unroll
        for (int j = 0; j < 4; j++) {
            const int c = tid + j * 256;
            const int row = c >> 4, nc = c & 15;
            cp16(Bb + (uint32_t)(row * BSTRB + nc * 16),
                 Bg + (size_t)(k0 + row) * Ndim + bn + nc * 8);
        }
    };

    const int NCH = Kdim / GBK;

    load_stage(0, 0); cp_commit();
    load_stage(1, 1); cp_commit();

    for (int i = 0; i < NCH; i++) {
        cp_wait<1>();
        __syncthreads();

        const int buf = i & 1;
        const uint32_t Ab = sb + buf * STAGE_B;
        const uint32_t Bb = Ab + A_STAGE_B;

        #pragma unroll
        for (int ks = 0; ks < 4; ks++) {     // 4 x k16 steps in BK=64
            uint32_t af[2][4], bf[8][2];
            #pragma unroll
            for (int mt = 0; mt < 2; mt++) {
                const uint32_t addr = Ab
                    + (uint32_t)((wm + mt * 16 + l15) * ASTRB)
                    + (uint32_t)(ks * 32 + lhi * 16);
                ldsm_x4(af[mt], addr);
            }
            #pragma unroll
            for (int np = 0; np < 4; np++) { // pairs of n8 tiles
                uint32_t r[4];
                const uint32_t addr = Bb
                    + (uint32_t)((ks * 16 + l15) * BSTRB)
                    + (uint32_t)((wn + np * 16 + lhi * 8) * 2);
                ldsm_x4_trans(r, addr);
                bf[2 * np][0] = r[0]; bf[2 * np][1] = r[1];
                bf[2 * np + 1][0] = r[2]; bf[2 * np + 1][1] = r[3];
            }
            #pragma unroll
            for (int mt = 0; mt < 2; mt++)
                #pragma unroll
                for (int nt = 0; nt < 8; nt++)
                    mma_f16(acc[mt][nt], af[mt], bf[nt]);
        }
        __syncthreads();

        if (i + 2 < NCH) load_stage(i + 2, (i + 2) & 1);
        cp_commit();   // always commit to keep group accounting aligned
    }

    // epilogue
    #pragma unroll
    for (int mt = 0; mt < 2; mt++) {
        const int row0 = bm + wm + mt * 16 + g;
        const int row1 = row0 + 8;
        if (PHASE == 1) {
            #pragma unroll
            for (int nt = 0; nt < 8; nt++) {
                const int col = bn + wn + nt * 8 + 2 * t;
                __half2 v0 = __floats2half2_rn(geluf(acc[mt][nt][0]), geluf(acc[mt][nt][1]));
                __half2 v1 = __floats2half2_rn(geluf(acc[mt][nt][2]), geluf(acc[mt][nt][3]));
                *(__half2*)(CoutH + (size_t)row0 * Ndim + col) = v0;
                *(__half2*)(CoutH + (size_t)row1 * Ndim + col) = v1;
            }
        } else {
            // out[row, n*BLK+col] = sum_i ph[n][i]*x[row, i*BLK+col] + w[n]*y
            float w0[4], w1[4], ph0[16], ph1[16];
            #pragma unroll
            for (int n = 0; n < 4; n++) {
                w0[n] = g_wout[row0 * 4 + n];
                w1[n] = g_wout[row1 * 4 + n];
            }
            #pragma unroll
            for (int q = 0; q < 16; q++) {
                ph0[q] = g_phi[row0 * 16 + q];
                ph1[q] = g_phi[row1 * 16 + q];
            }
            #pragma unroll
            for (int nt = 0; nt < 8; nt++) {
                const int col = bn + wn + nt * 8 + 2 * t;
                float2 xa0[4], xa1[4];
                #pragma unroll
                for (int ii = 0; ii < 4; ii++) {
                    xa0[ii] = *(const float2*)(xg + (size_t)row0 * IN_DIM + ii * BLK + col);
                    xa1[ii] = *(const float2*)(xg + (size_t)row1 * IN_DIM + ii * BLK + col);
                }
                #pragma unroll
                for (int n = 0; n < 4; n++) {
                    float2 o0, o1;
                    o0.x = fmaf(w0[n], acc[mt][nt][0],
                           fmaf(ph0[n*4+0], xa0[0].x, fmaf(ph0[n*4+1], xa0[1].x,
                           fmaf(ph0[n*4+2], xa0[2].x, ph0[n*4+3] * xa0[3].x))));
                    o0.y = fmaf(w0[n], acc[mt][nt][1],
                           fmaf(ph0[n*4+0], xa0[0].y, fmaf(ph0[n*4+1], xa0[1].y,
                           fmaf(ph0[n*4+2], xa0[2].y, ph0[n*4+3] * xa0[3].y))));
                    o1.x = fmaf(w1[n], acc[mt][nt][2],
                           fmaf(ph1[n*4+0], xa1[0].x, fmaf(ph1[n*4+1], xa1[1].x,
                           fmaf(ph1[n*4+2], xa1[2].x, ph1[n*4+3] * xa1[3].x))));
                    o1.y = fmaf(w1[n], acc[mt][nt][3],
                           fmaf(ph1[n*4+0], xa1[0].y, fmaf(ph1[n*4+1], xa1[1].y,
                           fmaf(ph1[n*4+2], xa1[2].y, ph1[n*4+3] * xa1[3].y))));
                    *(float2*)(CoutF + (size_t)row0 * IN_DIM + n * BLK + col) = o0;
                    *(float2*)(CoutF + (size_t)row1 * IN_DIM + n * BLK + col) = o1;
                }
            }
        }
    }
}

// ---------------------------------------------------------------------------
extern "C" void kernel_launch(void* const* d_in, const int* in_sizes, int n_in,
                              void* d_out, int out_size)
{
    const float* x      = (const float*)d_in[0];
    const float* p_ri   = (const float*)d_in[1];
    const float* p_wo   = (const float*)d_in[2];
    const float* a_ri   = (const float*)d_in[3];
    const float* a_wo   = (const float*)d_in[4];
    const float* W_ri   = (const float*)d_in[5];
    const float* W_wo   = (const float*)d_in[6];
    const float* ldt_c  = (const float*)d_in[7];
    const float* ldt_d  = (const float*)d_in[8];
    const float* W_dtc  = (const float*)d_in[9];
    const float* b_dtc  = (const float*)d_in[10];
    const float* W_dtd  = (const float*)d_in[11];
    const float* b_dtd  = (const float*)d_in[12];
    const float* cA     = (const float*)d_in[13];
    const float* W_conv = (const float*)d_in[14];
    const float* ddiag  = (const float*)d_in[15];
    const float* W_diss = (const float*)d_in[16];
    const float* W1     = (const float*)d_in[17];
    const float* W2     = (const float*)d_in[18];
    float* out = (float*)d_out;

    __half *gH, *gBr, *gW1h, *gW2h;
    cudaGetSymbolAddress((void**)&gH,   g_H);
    cudaGetSymbolAddress((void**)&gBr,  g_branch);
    cudaGetSymbolAddress((void**)&gW1h, g_W1h);
    cudaGetSymbolAddress((void**)&gW2h, g_W2h);

    cudaFuncSetAttribute(kernelA, cudaFuncAttributeMaxDynamicSharedMemorySize, 4 * IN_DIM * 4);
    cudaFuncSetAttribute(tc_gemm<EMBED, DFF, 1>, cudaFuncAttributeMaxDynamicSharedMemorySize, GEMM_SMEM);
    cudaFuncSetAttribute(tc_gemm<DFF, EMBED, 2>, cudaFuncAttributeMaxDynamicSharedMemorySize, GEMM_SMEM);

    const int n4 = (EMBED * DFF) / 4;
    f16_copy4<<<(n4 + 255) / 256, 256>>>((const float4*)W1, (uint2*)gW1h, n4);
    f16_copy4<<<(n4 + 255) / 256, 256>>>((const float4*)W2, (uint2*)gW2h, n4);

    const int nsm4 = 30 * IN_DIM / 4;
    pack_wsm<<<(nsm4 + 255) / 256, 256>>>(W_ri, W_wo, W_conv, W_diss, W_dtc, W_dtd);

    kernelA<<<BSZ / 4, 256, 4 * IN_DIM * 4>>>(
        x, p_ri, p_wo, a_ri, a_wo,
        ldt_c, ldt_d, b_dtc, b_dtd, cA, ddiag);

    tc_gemm<EMBED, DFF, 1><<<dim3(DFF / GBN, BSZ / GBM), 256, GEMM_SMEM>>>(gBr, gW1h, gH, nullptr, nullptr);
    tc_gemm<DFF, EMBED, 2><<<dim3(EMBED / GBN, BSZ / GBM), 256, GEMM_SMEM>>>(gH, gW2h, nullptr, out, x);
}

// round 17
// speedup vs baseline: 1.1235x; 1.1235x over previous
#include <cuda_runtime.h>
#include <cuda_fp16.h>
#include <math.h>
#include <stdint.h>

// Problem constants
#define BSZ    4096
#define NST    4
#define EMBED  2048
#define DFF    8192
#define IN_DIM 8192   // N*BLOCK = 4*2048
#define BLK    2048

// Scratch (device globals; no allocations allowed)
__device__ __half g_branch[(size_t)BSZ * EMBED];  // 16 MB fp16
__device__ __half g_H[(size_t)BSZ * DFF];         // 64 MB fp16
__device__ float  g_wout[BSZ * NST];
__device__ float  g_phi[BSZ * 16];                // per-row Phi (4x4)
__device__ __half g_W1h[(size_t)EMBED * DFF];     // fp16(W1) [2048, 8192]
__device__ __half g_W2h[(size_t)DFF * EMBED];     // fp16(W2) [8192, 2048]
__device__ __half g_Wsm[30 * IN_DIM];             // packed small weights (fp16)

// ---------------------------------------------------------------------------
// Math helpers
// ---------------------------------------------------------------------------
__device__ __forceinline__ float sigf(float v) { return 1.0f / (1.0f + expf(-v)); }
__device__ __forceinline__ float softplusf(float v) {
    return (v > 15.0f) ? v : log1pf(expf(v));
}
__device__ __forceinline__ float geluf(float v) {
    const float c = 0.7978845608028654f;
    float t = tanhf(c * (v + 0.044715f * v * v * v));
    return 0.5f * v * (1.0f + t);
}
__device__ __forceinline__ void mma_f16(float* c, const uint32_t* a, const uint32_t* b) {
    asm volatile("mma.sync.aligned.m16n8k16.row.col.f32.f16.f16.f32 "
                 "{%0,%1,%2,%3}, {%4,%5,%6,%7}, {%8,%9}, {%0,%1,%2,%3};"
                 : "+f"(c[0]), "+f"(c[1]), "+f"(c[2]), "+f"(c[3])
                 : "r"(a[0]), "r"(a[1]), "r"(a[2]), "r"(a[3]),
                   "r"(b[0]), "r"(b[1]));
}
__device__ __forceinline__ void ldsm_x4(uint32_t* r, uint32_t addr) {
    asm volatile("ldmatrix.sync.aligned.m8n8.x4.shared.b16 {%0,%1,%2,%3}, [%4];"
                 : "=r"(r[0]), "=r"(r[1]), "=r"(r[2]), "=r"(r[3]) : "r"(addr));
}
__device__ __forceinline__ void ldsm_x4_trans(uint32_t* r, uint32_t addr) {
    asm volatile("ldmatrix.sync.aligned.m8n8.x4.trans.shared.b16 {%0,%1,%2,%3}, [%4];"
                 : "=r"(r[0]), "=r"(r[1]), "=r"(r[2]), "=r"(r[3]) : "r"(addr));
}
__device__ __forceinline__ void cp16(uint32_t s, const void* g) {
    asm volatile("cp.async.cg.shared.global [%0], [%1], 16;" :: "r"(s), "l"(g));
}
__device__ __forceinline__ void cp_commit() {
    asm volatile("cp.async.commit_group;" ::: "memory");
}
template<int N>
__device__ __forceinline__ void cp_wait() {
    asm volatile("cp.async.wait_group %0;" :: "n"(N) : "memory");
}
__device__ __forceinline__ uint32_t smem_u32(const void* p) {
    uint32_t a;
    asm("{ .reg .u64 t; cvta.to.shared.u64 t, %1; cvt.u32.u64 %0, t; }" : "=r"(a) : "l"(p));
    return a;
}

// ---------------------------------------------------------------------------
// f32 -> f16 weight conversion (W1 / W2)
// ---------------------------------------------------------------------------
__global__ void __launch_bounds__(256) f16_copy4(const float4* __restrict__ src,
                                                 uint2* __restrict__ dst, int n4)
{
    int i = blockIdx.x * blockDim.x + threadIdx.x;
    if (i < n4) {
        float4 v = src[i];
        __half2 h0 = __floats2half2_rn(v.x, v.y);
        __half2 h1 = __floats2half2_rn(v.z, v.w);
        uint2 o;
        o.x = *(uint32_t*)&h0;
        o.y = *(uint32_t*)&h1;
        dst[i] = o;
    }
}

// ---------------------------------------------------------------------------
// Pack small weights to fp16 in dot-index order:
// j: 0-3 W_ri, 4-7 W_wo, 8-23 W_conv, 24-27 W_diss, 28 W_dtc, 29 W_dtd
// ---------------------------------------------------------------------------
__global__ void __launch_bounds__(256) pack_wsm(
    const float* __restrict__ W_ri,  const float* __restrict__ W_wo,
    const float* __restrict__ W_conv, const float* __restrict__ W_diss,
    const float* __restrict__ W_dtc, const float* __restrict__ W_dtd)
{
    const int i = blockIdx.x * blockDim.x + threadIdx.x;   // float4 units
    const int total = 30 * IN_DIM / 4;
    if (i >= total) return;
    const int j  = i / (IN_DIM / 4);
    const int kc = i % (IN_DIM / 4);
    const float* src;
    if (j < 4)        src = W_ri   + (size_t)j        * IN_DIM;
    else if (j < 8)   src = W_wo   + (size_t)(j - 4)  * IN_DIM;
    else if (j < 24)  src = W_conv + (size_t)(j - 8)  * IN_DIM;
    else if (j < 28)  src = W_diss + (size_t)(j - 24) * IN_DIM;
    else if (j == 28) src = W_dtc;
    else              src = W_dtd;
    float4 v = *(const float4*)(src + kc * 4);
    __half2 h0 = __floats2half2_rn(v.x, v.y);
    __half2 h1 = __floats2half2_rn(v.z, v.w);
    uint2 o;
    o.x = *(uint32_t*)&h0;
    o.y = *(uint32_t*)&h1;
    *(uint2*)(g_Wsm + (size_t)j * IN_DIM + kc * 4) = o;
}

// ---------------------------------------------------------------------------
// Kernel A: 4 rows per CTA, 512 threads (16 warps), 2 dots per warp,
// half2-vectorized weight loads. Writes g_branch, g_wout, g_phi.
// ---------------------------------------------------------------------------
__global__ void __launch_bounds__(512) kernelA(
    const float* __restrict__ x,
    const float* __restrict__ p_ri,   const float* __restrict__ p_wo,
    const float* __restrict__ a_ri,   const float* __restrict__ a_wo,
    const float* __restrict__ ldt_c,  const float* __restrict__ ldt_d,
    const float* __restrict__ b_dtc,  const float* __restrict__ b_dtd,
    const float* __restrict__ cA,     const float* __restrict__ ddiag)
{
    extern __shared__ float sx[];          // [4 * IN_DIM] = 128KB
    __shared__ float sdots[32][4];
    __shared__ float srin[4][4];

    const int row0 = blockIdx.x * 4;
    const int tid = threadIdx.x;
    const int w = tid >> 5, lane = tid & 31;

    {
        const float4* xr = (const float4*)(x + (size_t)row0 * IN_DIM);
        float4* sx4 = (float4*)sx;
        #pragma unroll 4
        for (int i = tid; i < 4 * IN_DIM / 4; i += 512) sx4[i] = xr[i];
    }
    __syncthreads();

    // warp w owns dots j = 2w, 2w+1 (j<31); j==30 -> sumsq, j==31 inactive
    const __half2* wp[2];
    int jidx[2];
    #pragma unroll
    for (int jj = 0; jj < 2; jj++) {
        const int j = w * 2 + jj;
        jidx[jj] = j;
        wp[jj] = (const __half2*)(g_Wsm + (size_t)((j < 30) ? j : 0) * IN_DIM);
    }

    float acc[2][4];   // [jj][row]
    #pragma unroll
    for (int a0 = 0; a0 < 2; a0++)
        #pragma unroll
        for (int a1 = 0; a1 < 4; a1++) acc[a0][a1] = 0.0f;

    const float2* sx2 = (const float2*)sx;
    const int HK = IN_DIM / 2;   // 4096 half2 elements per row

    #pragma unroll 4
    for (int k2 = lane; k2 < HK; k2 += 32) {
        const float2 x0 = sx2[k2];
        const float2 x1 = sx2[HK + k2];
        const float2 x2 = sx2[2 * HK + k2];
        const float2 x3 = sx2[3 * HK + k2];
        #pragma unroll
        for (int jj = 0; jj < 2; jj++) {
            if (jidx[jj] == 30) {
                acc[jj][0] = fmaf(x0.x, x0.x, fmaf(x0.y, x0.y, acc[jj][0]));
                acc[jj][1] = fmaf(x1.x, x1.x, fmaf(x1.y, x1.y, acc[jj][1]));
                acc[jj][2] = fmaf(x2.x, x2.x, fmaf(x2.y, x2.y, acc[jj][2]));
                acc[jj][3] = fmaf(x3.x, x3.x, fmaf(x3.y, x3.y, acc[jj][3]));
            } else if (jidx[jj] < 30) {
                const float2 wv = __half22float2(__ldg(wp[jj] + k2));
                acc[jj][0] = fmaf(wv.x, x0.x, fmaf(wv.y, x0.y, acc[jj][0]));
                acc[jj][1] = fmaf(wv.x, x1.x, fmaf(wv.y, x1.y, acc[jj][1]));
                acc[jj][2] = fmaf(wv.x, x2.x, fmaf(wv.y, x2.y, acc[jj][2]));
                acc[jj][3] = fmaf(wv.x, x3.x, fmaf(wv.y, x3.y, acc[jj][3]));
            }
        }
    }

    #pragma unroll
    for (int jj = 0; jj < 2; jj++)
        #pragma unroll
        for (int r = 0; r < 4; r++) {
            float v = acc[jj][r];
            #pragma unroll
            for (int o = 16; o > 0; o >>= 1) v += __shfl_down_sync(0xffffffffu, v, o);
            if (lane == 0) sdots[w * 2 + jj][r] = v;
        }
    __syncthreads();

    if (tid < 4) {
        const int r = tid;
        const int row = row0 + r;
        const float rstd = rsqrtf(sdots[30][r] * (1.0f / (float)IN_DIM) + 1.1920929e-7f);
        float h[30];
        #pragma unroll
        for (int j = 0; j < 30; j++) h[j] = sdots[j][r] * rstd;

        const float ari = a_ri[0], awo = a_wo[0];
        #pragma unroll
        for (int n = 0; n < 4; n++) {
            srin[r][n] = sigf(ari * h[n] + p_ri[n]);
            g_wout[row * 4 + n] = 2.0f * sigf(awo * h[4 + n] + p_wo[n]);
        }

        const float dtc = 1e-3f + 0.999f * sigf(ldt_c[0] + h[28] + b_dtc[0]);
        const float dtd = 1e-3f + 0.999f * sigf(ldt_d[0] + h[29] + b_dtd[0]);

        float Mm[4][4];
        #pragma unroll
        for (int i = 0; i < 4; i++)
            #pragma unroll
            for (int j = 0; j < 4; j++)
                Mm[i][j] = cA[i * 4 + j] + h[8 + i * 4 + j];

        float S[4][4];
        #pragma unroll
        for (int i = 0; i < 4; i++)
            #pragma unroll
            for (int j = 0; j < 4; j++)
                S[i][j] = 0.5f * (Mm[i][j] - Mm[j][i]) * dtc;

        float ehD[4];
        #pragma unroll
        for (int n = 0; n < 4; n++) {
            float dd = softplusf(ddiag[n] + h[24 + n]);
            ehD[n] = expf(-0.5f * dtd * dd);
        }

        float A[4][4], X[4][4];
        #pragma unroll
        for (int i = 0; i < 4; i++)
            #pragma unroll
            for (int j = 0; j < 4; j++) {
                float id = (i == j) ? 1.0f : 0.0f;
                A[i][j] = id - S[i][j];
                X[i][j] = id + S[i][j];
            }
        #pragma unroll
        for (int p = 0; p < 4; p++) {
            float inv = 1.0f / A[p][p];
            #pragma unroll
            for (int j = 0; j < 4; j++) { A[p][j] *= inv; X[p][j] *= inv; }
            #pragma unroll
            for (int rr = 0; rr < 4; rr++) {
                if (rr == p) continue;
                float f = A[rr][p];
                #pragma unroll
                for (int j = 0; j < 4; j++) {
                    A[rr][j] = fmaf(-f, A[p][j], A[rr][j]);
                    X[rr][j] = fmaf(-f, X[p][j], X[rr][j]);
                }
            }
        }
        #pragma unroll
        for (int i = 0; i < 4; i++)
            #pragma unroll
            for (int j = 0; j < 4; j++)
                g_phi[row * 16 + i * 4 + j] = ehD[i] * X[i][j] * ehD[j];
    }
    __syncthreads();

    // Phase 3: branch only (fp16)
    #pragma unroll
    for (int r = 0; r < 4; r++) {
        const int row = row0 + r;
        const float* sxr = sx + r * IN_DIM;
        const float r0 = srin[r][0], r1 = srin[r][1], r2 = srin[r][2], r3 = srin[r][3];
        for (int c = tid; c < BLK; c += 512) {
            float x0 = sxr[c], x1 = sxr[BLK + c], x2 = sxr[2 * BLK + c], x3 = sxr[3 * BLK + c];
            g_branch[(size_t)row * BLK + c] =
                __float2half_rn(r0 * x0 + r1 * x1 + r2 * x2 + r3 * x3);
        }
    }
}

// ---------------------------------------------------------------------------
// FP16 mma.sync GEMM (R15 mainloop): CTA 128x128, BK=64, 256 threads
// (8 warps, warp 32x64), 2-stage cp.async, 2 CTAs/SM.
// PHASE 1: g_H = f16(gelu(g_branch @ W1h))           (Kdim=2048, Ndim=8192)
// PHASE 2: out = Phi@x + wout * (g_H @ W2h) (pure store; Kdim=8192, Ndim=2048)
// ---------------------------------------------------------------------------
#define GBM 128
#define GBN 128
#define GBK 64
#define ASTRB 144                    // bytes/row: 64 fp16 + 8 pad
#define BSTRB 272                    // bytes/row: 128 fp16 + 8 pad
#define A_STAGE_B (GBM * ASTRB)      // 18432 B
#define B_STAGE_B (GBK * BSTRB)      // 17408 B
#define STAGE_B   (A_STAGE_B + B_STAGE_B)   // 35840 B
#define GEMM_SMEM (2 * STAGE_B)             // 71680 B -> 2 CTAs/SM = 143KB

template<int Kdim, int Ndim, int PHASE>
__global__ void __launch_bounds__(256, 2) tc_gemm(
    const __half* __restrict__ Ag,
    const __half* __restrict__ Bg,
    __half* __restrict__ CoutH,      // PHASE 1 target
    float* __restrict__ CoutF,       // PHASE 2 target
    const float* __restrict__ xg)    // PHASE 2: original x (for Phi@x)
{
    extern __shared__ char smem[];
    const uint32_t sb = smem_u32(smem);

    const int tid  = threadIdx.x;
    const int wid  = tid >> 5;
    const int lane = tid & 31;
    const int g = lane >> 2, t = lane & 3;
    const int l15 = lane & 15;
    const int lhi = lane >> 4;           // 0/1
    const int wm = (wid & 3) * 32;       // 4 warps along M (128)
    const int wn = (wid >> 2) * 64;      // 2 warps along N (128)
    const int bm = blockIdx.y * GBM;
    const int bn = blockIdx.x * GBN;

    // accumulators: warp tile 32x64 -> mt=2 (m16), nt=8 (n8) = 64 regs
    float acc[2][8][4];
    #pragma unroll
    for (int i = 0; i < 2; i++)
        #pragma unroll
        for (int j = 0; j < 8; j++)
            #pragma unroll
            for (int q = 0; q < 4; q++) acc[i][j][q] = 0.0f;

    auto load_stage = [&](int stage, int buf) {
        const uint32_t Ab = sb + buf * STAGE_B;
        const uint32_t Bb = Ab + A_STAGE_B;
        const int k0 = stage * GBK;
        // A: 128 rows x 8 16B-chunks = 1024 chunks, 4/thread
        #pragma unroll
        for (int j = 0; j < 4; j++) {
            const int c = tid + j * 256;
            const int row = c >> 3, kc = c & 7;
            cp16(Ab + (uint32_t)(row * ASTRB + kc * 16),
                 Ag + (size_t)(bm + row) * Kdim + k0 + kc * 8);
        }
        // B: 64 rows x 16 16B-chunks (128 fp16/row) = 1024 chunks, 4/thread
        #pragma unroll
        for (int j = 0; j < 4; j++) {
            const int c = tid + j * 256;
            const int row = c >> 4, nc = c & 15;
            cp16(Bb + (uint32_t)(row * BSTRB + nc * 16),
                 Bg + (size_t)(k0 + row) * Ndim + bn + nc * 8);
        }
    };

    const int NCH = Kdim / GBK;

    load_stage(0, 0); cp_commit();
    load_stage(1, 1); cp_commit();

    for (int i = 0; i < NCH; i++) {
        cp_wait<1>();
        __syncthreads();

        const int buf = i & 1;
        const uint32_t Ab = sb + buf * STAGE_B;
        const uint32_t Bb = Ab + A_STAGE_B;

        #pragma unroll
        for (int ks = 0; ks < 4; ks++) {     // 4 x k16 steps in BK=64
            uint32_t af[2][4], bf[8][2];
            #pragma unroll
            for (int mt = 0; mt < 2; mt++) {
                const uint32_t addr = Ab
                    + (uint32_t)((wm + mt * 16 + l15) * ASTRB)
                    + (uint32_t)(ks * 32 + lhi * 16);
                ldsm_x4(af[mt], addr);
            }
            #pragma unroll
            for (int np = 0; np < 4; np++) { // pairs of n8 tiles
                uint32_t r[4];
                const uint32_t addr = Bb
                    + (uint32_t)((ks * 16 + l15) * BSTRB)
                    + (uint32_t)((wn + np * 16 + lhi * 8) * 2);
                ldsm_x4_trans(r, addr);
                bf[2 * np][0] = r[0]; bf[2 * np][1] = r[1];
                bf[2 * np + 1][0] = r[2]; bf[2 * np + 1][1] = r[3];
            }
            #pragma unroll
            for (int mt = 0; mt < 2; mt++)
                #pragma unroll
                for (int nt = 0; nt < 8; nt++)
                    mma_f16(acc[mt][nt], af[mt], bf[nt]);
        }
        __syncthreads();

        if (i + 2 < NCH) load_stage(i + 2, (i + 2) & 1);
        cp_commit();   // always commit to keep group accounting aligned
    }

    // epilogue
    #pragma unroll
    for (int mt = 0; mt < 2; mt++) {
        const int row0 = bm + wm + mt * 16 + g;
        const int row1 = row0 + 8;
        if (PHASE == 1) {
            #pragma unroll
            for (int nt = 0; nt < 8; nt++) {
                const int col = bn + wn + nt * 8 + 2 * t;
                __half2 v0 = __floats2half2_rn(geluf(acc[mt][nt][0]), geluf(acc[mt][nt][1]));
                __half2 v1 = __floats2half2_rn(geluf(acc[mt][nt][2]), geluf(acc[mt][nt][3]));
                *(__half2*)(CoutH + (size_t)row0 * Ndim + col) = v0;
                *(__half2*)(CoutH + (size_t)row1 * Ndim + col) = v1;
            }
        } else {
            // out[row, n*BLK+col] = sum_i ph[n][i]*x[row, i*BLK+col] + w[n]*y
            float w0[4], w1[4], ph0[16], ph1[16];
            #pragma unroll
            for (int n = 0; n < 4; n++) {
                w0[n] = g_wout[row0 * 4 + n];
                w1[n] = g_wout[row1 * 4 + n];
            }
            #pragma unroll
            for (int q = 0; q < 16; q++) {
                ph0[q] = g_phi[row0 * 16 + q];
                ph1[q] = g_phi[row1 * 16 + q];
            }
            #pragma unroll
            for (int nt = 0; nt < 8; nt++) {
                const int col = bn + wn + nt * 8 + 2 * t;
                float2 xa0[4], xa1[4];
                #pragma unroll
                for (int ii = 0; ii < 4; ii++) {
                    xa0[ii] = *(const float2*)(xg + (size_t)row0 * IN_DIM + ii * BLK + col);
                    xa1[ii] = *(const float2*)(xg + (size_t)row1 * IN_DIM + ii * BLK + col);
                }
                #pragma unroll
                for (int n = 0; n < 4; n++) {
                    float2 o0, o1;
                    o0.x = fmaf(w0[n], acc[mt][nt][0],
                           fmaf(ph0[n*4+0], xa0[0].x, fmaf(ph0[n*4+1], xa0[1].x,
                           fmaf(ph0[n*4+2], xa0[2].x, ph0[n*4+3] * xa0[3].x))));
                    o0.y = fmaf(w0[n], acc[mt][nt][1],
                           fmaf(ph0[n*4+0], xa0[0].y, fmaf(ph0[n*4+1], xa0[1].y,
                           fmaf(ph0[n*4+2], xa0[2].y, ph0[n*4+3] * xa0[3].y))));
                    o1.x = fmaf(w1[n], acc[mt][nt][2],
                           fmaf(ph1[n*4+0], xa1[0].x, fmaf(ph1[n*4+1], xa1[1].x,
                           fmaf(ph1[n*4+2], xa1[2].x, ph1[n*4+3] * xa1[3].x))));
                    o1.y = fmaf(w1[n], acc[mt][nt][3],
                           fmaf(ph1[n*4+0], xa1[0].y, fmaf(ph1[n*4+1], xa1[1].y,
                           fmaf(ph1[n*4+2], xa1[2].y, ph1[n*4+3] * xa1[3].y))));
                    *(float2*)(CoutF + (size_t)row0 * IN_DIM + n * BLK + col) = o0;
                    *(float2*)(CoutF + (size_t)row1 * IN_DIM + n * BLK + col) = o1;
                }
            }
        }
    }
}

// ---------------------------------------------------------------------------
extern "C" void kernel_launch(void* const* d_in, const int* in_sizes, int n_in,
                              void* d_out, int out_size)
{
    const float* x      = (const float*)d_in[0];
    const float* p_ri   = (const float*)d_in[1];
    const float* p_wo   = (const float*)d_in[2];
    const float* a_ri   = (const float*)d_in[3];
    const float* a_wo   = (const float*)d_in[4];
    const float* W_ri   = (const float*)d_in[5];
    const float* W_wo   = (const float*)d_in[6];
    const float* ldt_c  = (const float*)d_in[7];
    const float* ldt_d  = (const float*)d_in[8];
    const float* W_dtc  = (const float*)d_in[9];
    const float* b_dtc  = (const float*)d_in[10];
    const float* W_dtd  = (const float*)d_in[11];
    const float* b_dtd  = (const float*)d_in[12];
    const float* cA     = (const float*)d_in[13];
    const float* W_conv = (const float*)d_in[14];
    const float* ddiag  = (const float*)d_in[15];
    const float* W_diss = (const float*)d_in[16];
    const float* W1     = (const float*)d_in[17];
    const float* W2     = (const float*)d_in[18];
    float* out = (float*)d_out;

    __half *gH, *gBr, *gW1h, *gW2h;
    cudaGetSymbolAddress((void**)&gH,   g_H);
    cudaGetSymbolAddress((void**)&gBr,  g_branch);
    cudaGetSymbolAddress((void**)&gW1h, g_W1h);
    cudaGetSymbolAddress((void**)&gW2h, g_W2h);

    cudaFuncSetAttribute(kernelA, cudaFuncAttributeMaxDynamicSharedMemorySize, 4 * IN_DIM * 4);
    cudaFuncSetAttribute(tc_gemm<EMBED, DFF, 1>, cudaFuncAttributeMaxDynamicSharedMemorySize, GEMM_SMEM);
    cudaFuncSetAttribute(tc_gemm<DFF, EMBED, 2>, cudaFuncAttributeMaxDynamicSharedMemorySize, GEMM_SMEM);

    const int n4 = (EMBED * DFF) / 4;
    f16_copy4<<<(n4 + 255) / 256, 256>>>((const float4*)W1, (uint2*)gW1h, n4);
    f16_copy4<<<(n4 + 255) / 256, 256>>>((const float4*)W2, (uint2*)gW2h, n4);

    const int nsm4 = 30 * IN_DIM / 4;
    pack_wsm<<<(nsm4 + 255) / 256, 256>>>(W_ri, W_wo, W_conv, W_diss, W_dtc, W_dtd);

    kernelA<<<BSZ / 4, 512, 4 * IN_DIM * 4>>>(
        x, p_ri, p_wo, a_ri, a_wo,
        ldt_c, ldt_d, b_dtc, b_dtd, cA, ddiag);

    tc_gemm<EMBED, DFF, 1><<<dim3(DFF / GBN, BSZ / GBM), 256, GEMM_SMEM>>>(gBr, gW1h, gH, nullptr, nullptr);
    tc_gemm<DFF, EMBED, 2><<<dim3(EMBED / GBN, BSZ / GBM), 256, GEMM_SMEM>>>(gH, gW2h, nullptr, out, x);
}